// round 2
// baseline (speedup 1.0000x reference)
#include <cuda_runtime.h>
#include <cuda_bf16.h>
#include <cstdint>

// Problem constants (match reference setup_inputs)
#define T_TABLES 8
#define N_ROWS   100000
#define EMB_D    128
#define N_BAGS_B 8192

// One warp per bag. Lane l owns floats [4l, 4l+4) of the D=128 row.
__global__ __launch_bounds__(256) void emb_bag_kernel(
    const int* __restrict__ indices,
    const int* __restrict__ offsets,
    const float* __restrict__ weights,
    float* __restrict__ out)
{
    const int warp = (blockIdx.x * blockDim.x + threadIdx.x) >> 5;
    const int lane = threadIdx.x & 31;
    const int num_bags = T_TABLES * N_BAGS_B;
    if (warp >= num_bags) return;

    const int t = warp / N_BAGS_B;   // table id
    const int b = warp % N_BAGS_B;   // bag id within table

    const int start = offsets[warp];
    const int end   = offsets[warp + 1];

    const float* __restrict__ wbase =
        weights + (long long)t * N_ROWS * EMB_D;

    float4 acc = make_float4(0.f, 0.f, 0.f, 0.f);

    int i = start;
    while (i < end) {
        const int n = min(32, end - i);
        // Coalesced index fetch: lane j holds indices[i + j]
        int myidx = 0;
        if (lane < n) myidx = indices[i + lane];

        if (n == 32) {
            #pragma unroll 8
            for (int j = 0; j < 32; ++j) {
                int r = __shfl_sync(0xffffffffu, myidx, j);
                r = max(0, min(r, N_ROWS - 1));   // safety clamp
                const float4 v =
                    __ldg(((const float4*)(wbase + (long long)r * EMB_D)) + lane);
                acc.x += v.x; acc.y += v.y; acc.z += v.z; acc.w += v.w;
            }
        } else {
            for (int j = 0; j < n; ++j) {
                int r = __shfl_sync(0xffffffffu, myidx, j);
                r = max(0, min(r, N_ROWS - 1));   // safety clamp
                const float4 v =
                    __ldg(((const float4*)(wbase + (long long)r * EMB_D)) + lane);
                acc.x += v.x; acc.y += v.y; acc.z += v.z; acc.w += v.w;
            }
        }
        i += n;
    }

    // Output layout: [B, T*D] feature-concatenated: out[b, t*D + d]
    float4* __restrict__ o =
        (float4*)(out + ((long long)b * T_TABLES + t) * EMB_D);
    o[lane] = acc;
}

extern "C" void kernel_launch(void* const* d_in, const int* in_sizes, int n_in,
                              void* d_out, int out_size)
{
    const int*   indices = (const int*)d_in[0];
    const int*   offsets = (const int*)d_in[1];
    const float* weights = (const float*)d_in[2];
    float*       out     = (float*)d_out;

    const int num_bags = T_TABLES * N_BAGS_B;          // 65536 warps
    const int threads  = 256;                          // 8 warps/CTA
    const int blocks   = (num_bags * 32 + threads - 1) / threads; // 8192

    emb_bag_kernel<<<blocks, threads>>>(indices, offsets, weights, out);
}

// round 3
// speedup vs baseline: 1.0570x; 1.0570x over previous
#include <cuda_runtime.h>
#include <cuda_bf16.h>
#include <cstdint>

// Problem constants (match reference setup_inputs)
#define T_TABLES 8
#define N_ROWS   100000
#define EMB_D    128
#define N_BAGS_B 8192

// One warp per bag. Lane l owns floats [4l, 4l+4) of the D=128 row.
__global__ __launch_bounds__(256) void emb_bag_kernel(
    const int* __restrict__ indices,
    const int* __restrict__ offsets,
    const float* __restrict__ weights,
    float* __restrict__ out)
{
    const int warp = (blockIdx.x * blockDim.x + threadIdx.x) >> 5;
    const int lane = threadIdx.x & 31;
    const int num_bags = T_TABLES * N_BAGS_B;
    if (warp >= num_bags) return;

    const int t = warp / N_BAGS_B;   // table id
    const int b = warp % N_BAGS_B;   // bag id within table

    const int start = offsets[warp];
    const int end   = offsets[warp + 1];

    // Table base as byte pointer; per-row offset fits in 32 bits (max 51.2MB).
    const char* __restrict__ wbase =
        (const char*)(weights + (long long)t * N_ROWS * EMB_D) +
        (unsigned)lane * 16u;

    float4 acc = make_float4(0.f, 0.f, 0.f, 0.f);

    int i = start;
    while (i < end) {
        const int n = min(32, end - i);
        // Coalesced index fetch: lane j holds indices[i + j]
        int myidx = 0;
        if (lane < n) myidx = indices[i + lane];

        if (n == 32) {
            #pragma unroll
            for (int j = 0; j < 32; ++j) {
                const unsigned r = (unsigned)__shfl_sync(0xffffffffu, myidx, j);
                const float4 v = __ldg((const float4*)(wbase + (r << 9)));
                acc.x += v.x; acc.y += v.y; acc.z += v.z; acc.w += v.w;
            }
        } else {
            for (int j = 0; j < n; ++j) {
                const unsigned r = (unsigned)__shfl_sync(0xffffffffu, myidx, j);
                const float4 v = __ldg((const float4*)(wbase + (r << 9)));
                acc.x += v.x; acc.y += v.y; acc.z += v.z; acc.w += v.w;
            }
        }
        i += n;
    }

    // Output layout: [B, T*D] feature-concatenated: out[b, t*D + d]
    float4* __restrict__ o =
        (float4*)(out + ((long long)b * T_TABLES + t) * EMB_D);
    o[lane] = acc;
}

extern "C" void kernel_launch(void* const* d_in, const int* in_sizes, int n_in,
                              void* d_out, int out_size)
{
    const int*   indices = (const int*)d_in[0];
    const int*   offsets = (const int*)d_in[1];
    const float* weights = (const float*)d_in[2];
    float*       out     = (float*)d_out;

    const int num_bags = T_TABLES * N_BAGS_B;          // 65536 warps
    const int threads  = 256;                          // 8 warps/CTA
    const int blocks   = (num_bags * 32 + threads - 1) / threads; // 8192

    emb_bag_kernel<<<blocks, threads>>>(indices, offsets, weights, out);
}

// round 4
// speedup vs baseline: 1.1874x; 1.1234x over previous
#include <cuda_runtime.h>
#include <cuda_bf16.h>
#include <cstdint>

// Problem constants (match reference setup_inputs)
#define T_TABLES 8
#define N_ROWS   100000
#define EMB_D    128
#define N_BAGS_B 8192

#define CTAS      592        // 148 SMs * 4 resident CTAs
#define THREADS   256        // 8 warps per CTA

// Persistent kernel: each warp grid-strides over bags.
// Lane l owns floats [4l, 4l+4) of the D=128 row.
__global__ __launch_bounds__(THREADS, 4) void emb_bag_kernel(
    const int* __restrict__ indices,
    const int* __restrict__ offsets,
    const float* __restrict__ weights,
    float* __restrict__ out)
{
    const int lane        = threadIdx.x & 31;
    const int warp0       = (blockIdx.x * THREADS + threadIdx.x) >> 5;
    const int total_warps = (CTAS * THREADS) >> 5;
    const int num_bags    = T_TABLES * N_BAGS_B;

    const char* __restrict__ wbytes =
        (const char*)weights + (unsigned)lane * 16u;

    // Prefetch state for the first bag handled by this warp.
    int bag = warp0;
    if (bag >= num_bags) return;

    int pf_start = offsets[bag];
    int pf_end   = offsets[bag + 1];
    int pf_idx   = (lane < pf_end - pf_start) ? indices[pf_start + lane] : 0;

    while (bag < num_bags) {
        const int t     = bag / N_BAGS_B;
        const int b     = bag - t * N_BAGS_B;
        const int start = pf_start;
        const int end   = pf_end;
        int       myidx = pf_idx;

        // Issue next bag's index/offset loads early so their latency hides
        // under this bag's gather burst.
        const int next_bag = bag + total_warps;
        if (next_bag < num_bags) {
            pf_start = offsets[next_bag];
            pf_end   = offsets[next_bag + 1];
            pf_idx   = (lane < pf_end - pf_start) ? indices[pf_start + lane] : 0;
        }

        // Table base: 64-bit once per bag; per-row offset is 32-bit (<51.2MB).
        const char* __restrict__ wbase =
            wbytes + (long long)t * (N_ROWS * EMB_D * 4ll);

        float4 acc = make_float4(0.f, 0.f, 0.f, 0.f);

        const int n0 = end - start;
        if (n0 == 32) {
            #pragma unroll
            for (int j = 0; j < 32; ++j) {
                const unsigned r = (unsigned)__shfl_sync(0xffffffffu, myidx, j);
                const float4 v = __ldg((const float4*)(wbase + (r << 9)));
                acc.x += v.x; acc.y += v.y; acc.z += v.z; acc.w += v.w;
            }
        } else {
            // Generic path: bags longer/shorter than 32.
            int i = start;
            int cur = myidx;
            int n = min(32, end - i);
            while (n > 0) {
                for (int j = 0; j < n; ++j) {
                    const unsigned r = (unsigned)__shfl_sync(0xffffffffu, cur, j);
                    const float4 v = __ldg((const float4*)(wbase + (r << 9)));
                    acc.x += v.x; acc.y += v.y; acc.z += v.z; acc.w += v.w;
                }
                i += n;
                n = min(32, end - i);
                if (n > 0) cur = (lane < n) ? indices[i + lane] : 0;
            }
        }

        // Output layout: [B, T*D] feature-concatenated: out[b, t*D + d]
        float4* __restrict__ o =
            (float4*)(out + ((long long)b * T_TABLES + t) * EMB_D);
        o[lane] = acc;

        bag = next_bag;
    }
}

extern "C" void kernel_launch(void* const* d_in, const int* in_sizes, int n_in,
                              void* d_out, int out_size)
{
    const int*   indices = (const int*)d_in[0];
    const int*   offsets = (const int*)d_in[1];
    const float* weights = (const float*)d_in[2];
    float*       out     = (float*)d_out;

    emb_bag_kernel<<<CTAS, THREADS>>>(indices, offsets, weights, out);
}